// round 7
// baseline (speedup 1.0000x reference)
#include <cuda_runtime.h>
#include <cuda_fp16.h>
#include <math.h>

#define NODES 50000
#define EDGES 800000
#define DIM   64

#define SCAN_B 512
#define NB ((NODES + SCAN_B - 1) / SCAN_B)   // 98 blocks — all co-resident on 148 SMs

// Scratch (no allocation allowed in kernel_launch)
__device__ float  g_agg[NODES * DIM];    // 12.8 MB (mean-aggregated, fp32)
__device__ float  g_h  [NODES * DIM];    // 12.8 MB
__device__ __half g_x16[NODES * DIM];    // 6.4 MB  (fp16 message copies)
__device__ __half g_h16[NODES * DIM];    // 6.4 MB
__device__ int    g_deg[NODES];
__device__ int    g_rowptr[NODES + 1];
__device__ int    g_cursor[NODES];
__device__ int    g_col[EDGES];          // 3.2 MB
__device__ int    g_bsum[NB];
__device__ int    g_arrive;              // spin-barrier arrival counter

// ---------------------------------------------------------------------------
// K1 (fused): convert x -> fp16, zero degrees, reset barrier counter.
// ---------------------------------------------------------------------------
__global__ void prep_kernel(const float* __restrict__ in) {
    int i = blockIdx.x * blockDim.x + threadIdx.x;      // quad index domain
    if (i < NODES * DIM / 4) {
        float4 v = __ldg(((const float4*)in) + i);
        ((__half2*)g_x16)[i * 2 + 0] = __floats2half2_rn(v.x, v.y);
        ((__half2*)g_x16)[i * 2 + 1] = __floats2half2_rn(v.z, v.w);
    }
    if (i < NODES) g_deg[i] = 0;
    if (i == 0)    g_arrive = 0;
}

// ---------------------------------------------------------------------------
// K2: degree histogram
// ---------------------------------------------------------------------------
__global__ void hist_kernel(const int* __restrict__ ei) {
    int e = blockIdx.x * blockDim.x + threadIdx.x;
    if (e >= EDGES) return;
    int dst = __ldg(&ei[EDGES + e]);
    if ((unsigned)dst < NODES) atomicAdd(&g_deg[dst], 1);
}

// ---------------------------------------------------------------------------
// K3: single-kernel exclusive scan of degrees -> rowptr + cursor.
// 98 blocks all resident -> spin barrier on g_arrive is safe.
// ---------------------------------------------------------------------------
__global__ void __launch_bounds__(SCAN_B) scan_kernel() {
    __shared__ int s[SCAN_B];
    __shared__ int sb[128];
    int tid = threadIdx.x;
    int b   = blockIdx.x;
    int i   = b * SCAN_B + tid;
    int d   = (i < NODES) ? g_deg[i] : 0;
    s[tid] = d;
    __syncthreads();
    // Hillis-Steele inclusive scan over the block
    for (int off = 1; off < SCAN_B; off <<= 1) {
        int v = (tid >= off) ? s[tid - off] : 0;
        __syncthreads();
        s[tid] += v;
        __syncthreads();
    }
    // publish block sum, arrive at grid barrier
    if (tid == SCAN_B - 1) {
        g_bsum[b] = s[tid];
        __threadfence();
        atomicAdd(&g_arrive, 1);
    }
    if (tid == 0) {
        while (*((volatile int*)&g_arrive) < NB) { }
    }
    __syncthreads();
    __threadfence();
    // exclusive prefix over block sums (all blocks redo it locally — trivial)
    if (tid < 128) sb[tid] = (tid < b) ? g_bsum[tid] : 0;   // tid<b implies tid<NB
    __syncthreads();
    for (int off = 64; off > 0; off >>= 1) {
        if (tid < off) sb[tid] += sb[tid + off];
        __syncthreads();
    }
    int offset = sb[0];
    if (i < NODES) {
        int excl = offset + s[tid] - d;
        g_rowptr[i] = excl;
        g_cursor[i] = excl;
        if (i == NODES - 1) g_rowptr[NODES] = offset + s[tid];
    }
}

// ---------------------------------------------------------------------------
// K4: fill CSR column array
// ---------------------------------------------------------------------------
__global__ void fill_kernel(const int* __restrict__ ei) {
    int e = blockIdx.x * blockDim.x + threadIdx.x;
    if (e >= EDGES) return;
    int src = __ldg(&ei[e]);
    int dst = __ldg(&ei[EDGES + e]);
    if ((unsigned)src >= NODES || (unsigned)dst >= NODES) return;
    int p = atomicAdd(&g_cursor[dst], 1);
    g_col[p] = src;
}

// ---------------------------------------------------------------------------
// Gather (fp16 messages), warp-per-node:
// lane = (pr<<4) | c : pair pr in {0,1} takes alternate neighbors, chunk c
// owns dims 4c..4c+3 (uint2 = 4 halves). Per-thread chain length = deg/2
// (2x latency hiding vs half-warp scheme); 4-way unrolled -> 8 neighbors
// in flight per warp iteration. Final combine: 4 shfl_xor(16).
// ---------------------------------------------------------------------------
__global__ void gather_kernel(const __half* __restrict__ feat16) {
    int warp = (blockIdx.x * blockDim.x + threadIdx.x) >> 5;
    if (warp >= NODES) return;
    int lane = threadIdx.x & 31;
    int c  = lane & 15;
    int pr = lane >> 4;

    int start = __ldg(&g_rowptr[warp]);
    int end   = __ldg(&g_rowptr[warp + 1]);

    float4 acc = make_float4(0.f, 0.f, 0.f, 0.f);

#define ACC_EDGE(uu)                                            \
    {  __half2 ph0 = *reinterpret_cast<__half2*>(&(uu).x);      \
       __half2 ph1 = *reinterpret_cast<__half2*>(&(uu).y);      \
       float2 f0 = __half22float2(ph0);                         \
       float2 f1 = __half22float2(ph1);                         \
       acc.x += f0.x; acc.y += f0.y; acc.z += f1.x; acc.w += f1.y; }

    int p = start + pr;
    for (; p + 6 < end; p += 8) {
        int s0 = __ldg(&g_col[p + 0]);
        int s1 = __ldg(&g_col[p + 2]);
        int s2 = __ldg(&g_col[p + 4]);
        int s3 = __ldg(&g_col[p + 6]);
        uint2 u0 = __ldg(((const uint2*)(feat16 + (size_t)s0 * DIM)) + c);
        uint2 u1 = __ldg(((const uint2*)(feat16 + (size_t)s1 * DIM)) + c);
        uint2 u2 = __ldg(((const uint2*)(feat16 + (size_t)s2 * DIM)) + c);
        uint2 u3 = __ldg(((const uint2*)(feat16 + (size_t)s3 * DIM)) + c);
        ACC_EDGE(u0); ACC_EDGE(u1); ACC_EDGE(u2); ACC_EDGE(u3);
    }
    for (; p < end; p += 2) {
        int s = __ldg(&g_col[p]);
        uint2 u = __ldg(((const uint2*)(feat16 + (size_t)s * DIM)) + c);
        ACC_EDGE(u);
    }
#undef ACC_EDGE

    // combine the two neighbor-halves
    acc.x += __shfl_xor_sync(0xffffffffu, acc.x, 16);
    acc.y += __shfl_xor_sync(0xffffffffu, acc.y, 16);
    acc.z += __shfl_xor_sync(0xffffffffu, acc.z, 16);
    acc.w += __shfl_xor_sync(0xffffffffu, acc.w, 16);

    if (pr == 0) {
        float inv = 1.0f / fmaxf((float)(end - start), 1.0f);
        acc.x *= inv; acc.y *= inv; acc.z *= inv; acc.w *= inv;
        ((float4*)(g_agg + (size_t)warp * DIM))[c] = acc;
    }
}

// ---------------------------------------------------------------------------
// Node transform (register-tiled): thread = 4 nodes x 4 dims, 64 nodes/block.
// Weights transposed into smem (pitch 65). Activations via gmem float4
// broadcast. Optionally writes an fp16 shadow of the output (layer 1 -> h16).
// ---------------------------------------------------------------------------
#define TN 64

template <bool APPLY_TANH, bool WRITE_H16>
__global__ void __launch_bounds__(256) transform_kernel(
        const float* __restrict__ agg,
        const float* __restrict__ xin,
        const float* __restrict__ Wl,
        const float* __restrict__ bl,
        const float* __restrict__ Wr,
        float* __restrict__ out) {
    __shared__ float sW[128 * 65];

    int tid = threadIdx.x;
    for (int i = tid; i < DIM * DIM; i += 256) {
        int dout = i >> 6, k = i & 63;
        sW[k * 65 + dout]        = __ldg(&Wl[i]);
        sW[(64 + k) * 65 + dout] = __ldg(&Wr[i]);
    }
    __syncthreads();

    int dt = tid & 15;
    int nt = tid >> 4;
    int d  = dt * 4;
    int n0 = blockIdx.x * TN + nt * 4;

    const float4* arow[4];
    const float4* xrow[4];
#pragma unroll
    for (int j = 0; j < 4; j++) {
        int n = n0 + j; if (n >= NODES) n = NODES - 1;
        arow[j] = (const float4*)(agg + (size_t)n * DIM);
        xrow[j] = (const float4*)(xin + (size_t)n * DIM);
    }

    float acc[4][4];
#pragma unroll
    for (int j = 0; j < 4; j++)
#pragma unroll
        for (int q = 0; q < 4; q++) acc[j][q] = 0.0f;

#pragma unroll
    for (int kq = 0; kq < 16; kq++) {
        float4 a0 = __ldg(arow[0] + kq);
        float4 a1 = __ldg(arow[1] + kq);
        float4 a2 = __ldg(arow[2] + kq);
        float4 a3 = __ldg(arow[3] + kq);
        const float av[4][4] = {{a0.x,a0.y,a0.z,a0.w},{a1.x,a1.y,a1.z,a1.w},
                                {a2.x,a2.y,a2.z,a2.w},{a3.x,a3.y,a3.z,a3.w}};
#pragma unroll
        for (int kk = 0; kk < 4; kk++) {
            int k = kq * 4 + kk;
            float w0 = sW[k * 65 + d + 0];
            float w1 = sW[k * 65 + d + 1];
            float w2 = sW[k * 65 + d + 2];
            float w3 = sW[k * 65 + d + 3];
#pragma unroll
            for (int j = 0; j < 4; j++) {
                acc[j][0] += av[j][kk] * w0;
                acc[j][1] += av[j][kk] * w1;
                acc[j][2] += av[j][kk] * w2;
                acc[j][3] += av[j][kk] * w3;
            }
        }
    }
#pragma unroll
    for (int kq = 0; kq < 16; kq++) {
        float4 a0 = __ldg(xrow[0] + kq);
        float4 a1 = __ldg(xrow[1] + kq);
        float4 a2 = __ldg(xrow[2] + kq);
        float4 a3 = __ldg(xrow[3] + kq);
        const float av[4][4] = {{a0.x,a0.y,a0.z,a0.w},{a1.x,a1.y,a1.z,a1.w},
                                {a2.x,a2.y,a2.z,a2.w},{a3.x,a3.y,a3.z,a3.w}};
#pragma unroll
        for (int kk = 0; kk < 4; kk++) {
            int k = 64 + kq * 4 + kk;
            float w0 = sW[k * 65 + d + 0];
            float w1 = sW[k * 65 + d + 1];
            float w2 = sW[k * 65 + d + 2];
            float w3 = sW[k * 65 + d + 3];
#pragma unroll
            for (int j = 0; j < 4; j++) {
                acc[j][0] += av[j][kk] * w0;
                acc[j][1] += av[j][kk] * w1;
                acc[j][2] += av[j][kk] * w2;
                acc[j][3] += av[j][kk] * w3;
            }
        }
    }

    float b0 = __ldg(&bl[d + 0]);
    float b1 = __ldg(&bl[d + 1]);
    float b2 = __ldg(&bl[d + 2]);
    float b3 = __ldg(&bl[d + 3]);

#pragma unroll
    for (int j = 0; j < 4; j++) {
        int n = n0 + j;
        if (n >= NODES) break;
        float4 r;
        r.x = acc[j][0] + b0;
        r.y = acc[j][1] + b1;
        r.z = acc[j][2] + b2;
        r.w = acc[j][3] + b3;
        if (APPLY_TANH) {
            r.x = tanhf(r.x); r.y = tanhf(r.y);
            r.z = tanhf(r.z); r.w = tanhf(r.w);
        }
        ((float4*)(out + (size_t)n * DIM))[dt] = r;
        if (WRITE_H16) {
            __half2* hp = (__half2*)(g_h16 + (size_t)n * DIM);
            hp[dt * 2 + 0] = __floats2half2_rn(r.x, r.y);
            hp[dt * 2 + 1] = __floats2half2_rn(r.z, r.w);
        }
    }
}

// ---------------------------------------------------------------------------
// Launch (8 kernels total)
// ---------------------------------------------------------------------------
extern "C" void kernel_launch(void* const* d_in, const int* in_sizes, int n_in,
                              void* d_out, int out_size) {
    const float* x    = (const float*)d_in[0];
    const int*   ei   = (const int*)d_in[1];
    const float* W_l1 = (const float*)d_in[2];
    const float* b_l1 = (const float*)d_in[3];
    const float* W_r1 = (const float*)d_in[4];
    const float* W_l2 = (const float*)d_in[5];
    const float* b_l2 = (const float*)d_in[6];
    const float* W_r2 = (const float*)d_in[7];
    float* out = (float*)d_out;

    float*  agg; cudaGetSymbolAddress((void**)&agg, g_agg);
    float*  h;   cudaGetSymbolAddress((void**)&h,   g_h);
    __half* x16; cudaGetSymbolAddress((void**)&x16, g_x16);
    __half* h16; cudaGetSymbolAddress((void**)&h16, g_h16);

    const int EB = 256, EG = (EDGES + EB - 1) / EB;
    const int PG = (NODES * DIM / 4 + 255) / 256;          // covers NODES too
    const int GG = (int)(((long long)NODES * 32 + 255) / 256);
    const int TG = (NODES + TN - 1) / TN;

    // CSR build + fp16 staging (reused by both layers)
    prep_kernel<<<PG, 256>>>(x);
    hist_kernel<<<EG, EB>>>(ei);
    scan_kernel<<<NB, SCAN_B>>>();
    fill_kernel<<<EG, EB>>>(ei);

    // Layer 1
    gather_kernel<<<GG, 256>>>(x16);
    transform_kernel<true, true><<<TG, 256>>>(agg, x, W_l1, b_l1, W_r1, h);

    // Layer 2
    gather_kernel<<<GG, 256>>>(h16);
    transform_kernel<false, false><<<TG, 256>>>(agg, h, W_l2, b_l2, W_r2, out);
}